// round 15
// baseline (speedup 1.0000x reference)
#include <cuda_runtime.h>
#include <cuda_fp16.h>
#include <math.h>
#include <stdint.h>

#define HH 256
#define PIT 80   // smem row pitch bytes: 5 x 16B -> conflict-free ldmatrix (5 coprime 8)

// ============================ helpers ============================
__device__ __forceinline__ uint32_t smem_u32(const void* p){
    uint32_t a;
    asm("{ .reg .u64 t; cvta.to.shared.u64 t, %1; cvt.u32.u64 %0, t; }" : "=r"(a) : "l"(p));
    return a;
}
__device__ __forceinline__ void ldsm4(uint32_t* d, uint32_t addr){
    asm volatile("ldmatrix.sync.aligned.m8n8.x4.shared.b16 {%0,%1,%2,%3}, [%4];"
        : "=r"(d[0]), "=r"(d[1]), "=r"(d[2]), "=r"(d[3]) : "r"(addr));
}
__device__ __forceinline__ void mma16816(float* c, const uint32_t* a, const uint32_t* b){
    asm volatile("mma.sync.aligned.m16n8k16.row.col.f32.f16.f16.f32 "
        "{%0,%1,%2,%3},{%4,%5,%6,%7},{%8,%9},{%0,%1,%2,%3};"
        : "+f"(c[0]), "+f"(c[1]), "+f"(c[2]), "+f"(c[3])
        : "r"(a[0]), "r"(a[1]), "r"(a[2]), "r"(a[3]), "r"(b[0]), "r"(b[1]));
}
__device__ __forceinline__ uint32_t pack_h2(float x0, float x1){
    __half2 h = __floats2half2_rn(x0, x1);
    uint32_t u; *(__half2*)&u = h; return u;
}
#define CPA16(d, s) asm volatile("cp.async.cg.shared.global [%0], [%1], 16;" :: "r"(d), "l"(s))
#define CP_COMMIT() asm volatile("cp.async.commit_group;" ::: "memory")
#define CP_WAIT0()  asm volatile("cp.async.wait_group 0;" ::: "memory")
#define CP_WAIT1()  asm volatile("cp.async.wait_group 1;" ::: "memory")

// ============================ device scratch ============================
__device__ __half g_WtH1[3][256 * 512];   // stage1 W^T fp16
__device__ __half g_WtH2[4][256 * 256];   // stage2 W1^T fp16
__device__ __half g_mH[2][16384 * HH];    // s1m, s2m (fp16)
__device__ __half g_rH[2][65536 * HH];    // s2r, s3r (fp16)
__device__ float g_part[4][2048];
__device__ float g_w[4];
__device__ int   g_inv[131072];

// ============================ tiny kernels ============================
__global__ void k_inv_scat(const int* __restrict__ mid, int m){
    int i = blockIdx.x * 256 + threadIdx.x;
    if (i < m) g_inv[mid[i]] = i;
}

// combined weight prep (fp16) + inv init:
//   z in [0,3): stage-1 (K=512), z in [3,7): stage-2 (K=256, blockIdx.y<8)
//   z == 7: initialize g_inv to -1 (128 blocks x 256 thr, strided)
__global__ void k_wprep(const float* __restrict__ g1W, const float* __restrict__ g2W,
                        const float* __restrict__ g3W,
                        const float* __restrict__ m1W1, const float* __restrict__ m2W1,
                        const float* __restrict__ r1W1, const float* __restrict__ r2W1,
                        int NN){
    __shared__ float t[32][33];
    const int z = blockIdx.z;
    if (z == 7){
        int base = (blockIdx.y * 8 + blockIdx.x) * 256 + threadIdx.y * 32 + threadIdx.x;
        for (int i = base; i < NN && i < 131072; i += 32768) g_inv[i] = -1;
        return;
    }
    const bool st1 = (z < 3);
    if (!st1 && blockIdx.y >= 8) return;
    const float* W;
    switch (z){
        case 0: W = g1W; break;
        case 1: W = g2W; break;
        case 2: W = g3W; break;
        case 3: W = m1W1; break;
        case 4: W = m2W1; break;
        case 5: W = r1W1; break;
        default: W = r2W1; break;
    }
    const int K = st1 ? 512 : 256;
    __half* hi = st1 ? g_WtH1[z] : g_WtH2[z - 3];
    int n0 = blockIdx.x * 32, k0 = blockIdx.y * 32;
    int tx = threadIdx.x, ty = threadIdx.y;
#pragma unroll
    for (int i = 0; i < 4; i++){
        int r = ty + i * 8;
        t[r][tx] = W[(long)(k0 + r) * 256 + n0 + tx];
    }
    __syncthreads();
#pragma unroll
    for (int i = 0; i < 4; i++){
        int r = ty + i * 8;
        hi[(long)(n0 + r) * K + k0 + tx] = __float2half_rn(t[tx][r]);
    }
}

// ==== stage 1 GEMM + fused pure-row copy (R13 structure) ====
// gemm: CTA tile 128x128, fp16 2-term, double-buffered, 2 CTA/SM
// blocks with blockIdx.y >= ytiles copy pure rows (inv<0 && row>=batch) of all 6 arrays
// dynamic smem: buf b at b*30720 { Ah@0, Al@10240, Bh@20480 }, bias @61440
#define G1_SMEM 62464
__global__ __launch_bounds__(256, 2)
void k_gemm1(const float* __restrict__ s1t, const float* __restrict__ s1s,
             const float* __restrict__ s2t, const float* __restrict__ s2me,
             const float* __restrict__ s3t, const float* __restrict__ s3me,
             const int* __restrict__ mid, const int* __restrict__ pbatch,
             const float* __restrict__ g1b, const float* __restrict__ g2b,
             const float* __restrict__ g3b, int Mrows,
             int ytiles, int cpyY, float4* __restrict__ out, int NN)
{
    extern __shared__ __align__(16) char smd[];
    const int z = blockIdx.z;
    const int batch = *pbatch;
    const int tid = threadIdx.x;

    // ---------------- fused copy path (streaming hints) ----------------
    if ((int)blockIdx.y >= ytiles){
        const int cb = ((z * cpyY + ((int)blockIdx.y - ytiles)) * 2 + (int)blockIdx.x);
        const int row0c = cb * 64;
        const long sz = (long)NN * 64;
        const float4* S1T = (const float4*)s1t;
        const float4* S1S = (const float4*)s1s;
        const float4* S2T = (const float4*)s2t;
        const float4* S2M = (const float4*)s2me;
        const float4* S3T = (const float4*)s3t;
        const float4* S3M = (const float4*)s3me;
#pragma unroll 1
        for (int p = 0; p < 16; p++){
            int idx = p * 256 + tid;
            int r = row0c + (idx >> 6);
            int lane = idx & 63;
            if (r >= NN) break;
            if (g_inv[r] >= 0 || r < batch) continue;   // mix rows -> k_output
            long o = (long)r * 64 + lane;
            __stcs(out + 0 * sz + o, __ldcs(S1T + o));
            __stcs(out + 1 * sz + o, __ldcs(S1S + o));
            __stcs(out + 2 * sz + o, __ldcs(S2T + o));
            __stcs(out + 3 * sz + o, __ldcs(S2M + o));
            __stcs(out + 4 * sz + o, __ldcs(S3T + o));
            __stcs(out + 5 * sz + o, __ldcs(S3M + o));
        }
        return;
    }

    // ---------------- gemm path ----------------
    const int R = (z < 2) ? Mrows : batch;
    const int row0 = blockIdx.y * 128;
    if (row0 >= R) return;
    const int n0 = blockIdx.x * 128;

    const float *A0, *A1, *bias;
    const __half *WH;
    __half *OH;
    if (z == 0)      { A0 = s1t; A1 = s1s;  bias = g1b; WH = g_WtH1[0]; OH = g_mH[0]; }
    else if (z == 1) { A0 = s2t; A1 = s2me; bias = g2b; WH = g_WtH1[1]; OH = g_mH[1]; }
    else if (z == 2) { A0 = s2t; A1 = s2me; bias = g2b; WH = g_WtH1[1]; OH = g_rH[0]; }
    else             { A0 = s3t; A1 = s3me; bias = g3b; WH = g_WtH1[2]; OH = g_rH[1]; }

    float* biasS = (float*)(smd + 61440);
    const int lane = tid & 31, wid = tid >> 5;
    const int q = lane >> 3, lr = lane & 7, wm = wid & 3, wn = wid >> 2;
    biasS[tid] = bias[tid];

    const int arw = tid >> 1, ahalf = tid & 1;
    int gr = row0 + arw; if (gr >= R) gr = R - 1;
    const long arow = ((z < 2) ? (long)mid[gr] : (long)gr) * HH;

    const uint32_t sbase = smem_u32(smd);
    const int hrow = tid >> 1, half = tid & 1;
    const __half* pBH = WH + (long)(n0 + hrow) * 512 + half * 16;
    const uint32_t bdst0 = sbase + 20480u + (uint32_t)hrow * PIT + (uint32_t)half * 32;
    const uint32_t adst0 = sbase + (uint32_t)arw * PIT + (uint32_t)ahalf * 32;

    float acc[2][8][4];
#pragma unroll
    for (int i = 0; i < 2; i++)
#pragma unroll
        for (int j = 0; j < 8; j++)
#pragma unroll
            for (int k = 0; k < 4; k++) acc[i][j][k] = 0.f;

    float4 pa0, pa1, pa2, pa3;    // A staging: 16 fp32 for one 32-K chunk

#define LOADA(c) { \
    const float* src = (((c) < 8) ? A0 : A1) + arow + (((c) & 7) * 32 + ahalf * 16); \
    pa0 = ((const float4*)src)[0]; pa1 = ((const float4*)src)[1]; \
    pa2 = ((const float4*)src)[2]; pa3 = ((const float4*)src)[3]; }

#define STSA(b) { \
    float f[16]; \
    *(float4*)&f[0] = pa0; *(float4*)&f[4] = pa1; *(float4*)&f[8] = pa2; *(float4*)&f[12] = pa3; \
    uint32_t hb[8], lb[8]; \
    _Pragma("unroll") \
    for (int j = 0; j < 8; j++){ \
        float x0 = f[2*j], x1 = f[2*j+1]; \
        __half2 h2 = __floats2half2_rn(x0, x1); \
        hb[j] = *(uint32_t*)&h2; \
        lb[j] = pack_h2(x0 - __half2float(__low2half(h2)), \
                        x1 - __half2float(__high2half(h2))); \
    } \
    uint32_t off = (adst0 - sbase) + (uint32_t)(b) * 30720u; \
    *(uint4*)(smd + off)         = *(uint4*)&hb[0]; \
    *(uint4*)(smd + off + 16)    = *(uint4*)&hb[4]; \
    *(uint4*)(smd + off + 10240) = *(uint4*)&lb[0]; \
    *(uint4*)(smd + off + 10256) = *(uint4*)&lb[4]; }

#define ISSUEB(c, b) { \
    uint32_t d = bdst0 + (uint32_t)(b) * 30720u; \
    CPA16(d,      pBH + (c) * 32); CPA16(d + 16, pBH + (c) * 32 + 8); \
    CP_COMMIT(); }

    // prologue
    LOADA(0); STSA(0);
    ISSUEB(0, 0); ISSUEB(1, 1);
    LOADA(1);

    for (int c = 0; c < 16; c++){
        if (c >= 14) CP_WAIT0(); else CP_WAIT1();
        __syncthreads();                       // B(c) + A(c) visible; prior compute done
        const uint32_t bb = sbase + (uint32_t)(c & 1) * 30720u;
#pragma unroll
        for (int s = 0; s < 2; s++){
            uint32_t ah[2][4], al[2][4];
#pragma unroll
            for (int mt = 0; mt < 2; mt++){
                uint32_t ra = (uint32_t)(wm * 32 + mt * 16 + (q & 1) * 8 + lr) * PIT
                            + (uint32_t)(s * 2 + (q >> 1)) * 16;
                ldsm4(ah[mt], bb + ra);
                ldsm4(al[mt], bb + 10240 + ra);
            }
#pragma unroll
            for (int g = 0; g < 4; g++){
                uint32_t rb = (uint32_t)(wn * 64 + g * 16 + (q >> 1) * 8 + lr) * PIT
                            + (uint32_t)(s * 2 + (q & 1)) * 16;
                uint32_t bh[4];
                ldsm4(bh, bb + 20480 + rb);
                mma16816(acc[0][2*g],   ah[0], bh);
                mma16816(acc[1][2*g],   ah[1], bh);
                mma16816(acc[0][2*g+1], ah[0], bh + 2);
                mma16816(acc[1][2*g+1], ah[1], bh + 2);
                mma16816(acc[0][2*g],   al[0], bh);
                mma16816(acc[1][2*g],   al[1], bh);
                mma16816(acc[0][2*g+1], al[0], bh + 2);
                mma16816(acc[1][2*g+1], al[1], bh + 2);
            }
        }
        if (c + 1 < 16) STSA((c + 1) & 1);     // convert staged A(c+1) into other buffer
        if (c + 2 < 16) LOADA(c + 2);          // stage A(c+2)
        __syncthreads();                       // A(c+1) visible; buf c&1 free for B(c+2)
        if (c + 2 < 16) ISSUEB(c + 2, c & 1);
    }
#undef LOADA
#undef STSA
#undef ISSUEB

    // epilogue: tanh + bias, store fp16 (hi only)
#pragma unroll
    for (int mt = 0; mt < 2; mt++){
#pragma unroll
        for (int nt = 0; nt < 8; nt++){
            const int ccol = n0 + wn * 64 + nt * 8 + (lane & 3) * 2;
            const float b0 = biasS[ccol & 255], b1 = biasS[(ccol + 1) & 255];
#pragma unroll
            for (int hf = 0; hf < 2; hf++){
                int grow = row0 + wm * 32 + mt * 16 + (lane >> 2) + hf * 8;
                if (grow < R){
                    float x0 = tanhf(acc[mt][nt][hf * 2]     + b0);
                    float x1 = tanhf(acc[mt][nt][hf * 2 + 1] + b1);
                    *(uint32_t*)(OH + (long)grow * HH + ccol) = pack_h2(x0, x1);
                }
            }
        }
    }
}

// ============================ stage 2 GEMM (fp16 1-term, cp.async) ============
__global__ __launch_bounds__(256, 2)
void k_gemm2(const int* __restrict__ pbatch,
             const float* __restrict__ m1b1, const float* __restrict__ m1W2,
             const float* __restrict__ m2b1, const float* __restrict__ m2W2,
             const float* __restrict__ r1b1, const float* __restrict__ r1W2,
             const float* __restrict__ r2b1, const float* __restrict__ r2W2,
             int Mrows)
{
    const int z = blockIdx.z;
    const int batch = *pbatch;
    const int R = (z < 2) ? Mrows : batch;
    const int row0 = blockIdx.y * 128;
    const int tid = threadIdx.x;
    const int pidx = blockIdx.y * 2 + blockIdx.x;
    if (row0 >= R){ if (tid == 0) g_part[z][pidx] = 0.f; return; }
    const int n0 = blockIdx.x * 128;

    const __half *XH, *WH = g_WtH2[z];
    const float *b1, *W2;
    if (z == 0)      { XH = g_mH[0]; b1 = m1b1; W2 = m1W2; }
    else if (z == 1) { XH = g_mH[1]; b1 = m2b1; W2 = m2W2; }
    else if (z == 2) { XH = g_rH[0]; b1 = r1b1; W2 = r1W2; }
    else             { XH = g_rH[1]; b1 = r2b1; W2 = r2W2; }

    // buf b at b*20480 { Ah@0, Bh@10240 }; b1S@40960, w2S@41984, red@43008
    __shared__ __align__(16) char sm[44032];
    float* b1S = (float*)(sm + 40960);
    float* w2S = (float*)(sm + 41984);
    float* red = (float*)(sm + 43008);

    const int lane = tid & 31, wid = tid >> 5;
    const int q = lane >> 3, lr = lane & 7, wm = wid & 3, wn = wid >> 2;
    b1S[tid] = b1[tid];
    w2S[tid] = W2[tid];

    const uint32_t sbase = smem_u32(sm);
    const int hrow = tid >> 1, half = tid & 1;
    const __half* pA = XH + (long)(row0 + hrow) * 256 + half * 16;
    const __half* pB = WH + (long)(n0 + hrow) * 256 + half * 16;
    const uint32_t dst0 = sbase + (uint32_t)hrow * PIT + (uint32_t)half * 32;

#define ISSUE2(c, b) { \
    uint32_t d = dst0 + (uint32_t)(b) * 20480u; \
    CPA16(d,         pA + (c) * 32); CPA16(d + 16,    pA + (c) * 32 + 8); \
    CPA16(d + 10240, pB + (c) * 32); CPA16(d + 10256, pB + (c) * 32 + 8); \
    CP_COMMIT(); }

    float acc[2][8][4];
#pragma unroll
    for (int i = 0; i < 2; i++)
#pragma unroll
        for (int j = 0; j < 8; j++)
#pragma unroll
            for (int k = 0; k < 4; k++) acc[i][j][k] = 0.f;

    ISSUE2(0, 0); ISSUE2(1, 1);

    for (int c = 0; c < 8; c++){
        if (c >= 6) CP_WAIT0(); else CP_WAIT1();
        __syncthreads();
        const uint32_t bb = sbase + (uint32_t)(c & 1) * 20480u;
#pragma unroll
        for (int s = 0; s < 2; s++){
            uint32_t ah[2][4];
#pragma unroll
            for (int mt = 0; mt < 2; mt++){
                uint32_t ra = (uint32_t)(wm * 32 + mt * 16 + (q & 1) * 8 + lr) * PIT
                            + (uint32_t)(s * 2 + (q >> 1)) * 16;
                ldsm4(ah[mt], bb + ra);
            }
#pragma unroll
            for (int g = 0; g < 4; g++){
                uint32_t rb = (uint32_t)(wn * 64 + g * 16 + (q >> 1) * 8 + lr) * PIT
                            + (uint32_t)(s * 2 + (q & 1)) * 16;
                uint32_t bh[4];
                ldsm4(bh, bb + 10240 + rb);
                mma16816(acc[0][2*g],   ah[0], bh);
                mma16816(acc[1][2*g],   ah[1], bh);
                mma16816(acc[0][2*g+1], ah[0], bh + 2);
                mma16816(acc[1][2*g+1], ah[1], bh + 2);
            }
        }
        __syncthreads();
        if (c + 2 < 8) ISSUE2(c + 2, c & 1);
    }
#undef ISSUE2

    float local = 0.f;
#pragma unroll
    for (int mt = 0; mt < 2; mt++){
#pragma unroll
        for (int nt = 0; nt < 8; nt++){
            const int ccol = n0 + wn * 64 + nt * 8 + (lane & 3) * 2;
            const float b0 = b1S[ccol & 255], bb1 = b1S[(ccol + 1) & 255];
            const float w0 = w2S[ccol & 255], w1 = w2S[(ccol + 1) & 255];
#pragma unroll
            for (int hf = 0; hf < 2; hf++){
                int grow = row0 + wm * 32 + mt * 16 + (lane >> 2) + hf * 8;
                if (grow < R){
                    local += tanhf(acc[mt][nt][hf * 2]     + b0)  * w0;
                    local += tanhf(acc[mt][nt][hf * 2 + 1] + bb1) * w1;
                }
            }
        }
    }
    red[tid] = local;
    __syncthreads();
    for (int st = 128; st > 0; st >>= 1){        // fixed-order tree: deterministic
        if (tid < st) red[tid] += red[tid + st];
        __syncthreads();
    }
    if (tid == 0) g_part[z][pidx] = red[0];
}

// ============================ reduce + softmax ============================
__global__ void k_reduce(const int* __restrict__ pbatch, int Mrows, int ntiles,
                         const float* __restrict__ b2a, const float* __restrict__ b2b,
                         const float* __restrict__ b2c, const float* __restrict__ b2d)
{
    __shared__ float sh[256];
    const int tid = threadIdx.x;
    float s[4];
#pragma unroll
    for (int zz = 0; zz < 4; zz++){
        float loc = 0.f;
        for (int i = tid; i < ntiles; i += 256) loc += g_part[zz][i];
        sh[tid] = loc;
        __syncthreads();
        for (int st = 128; st > 0; st >>= 1){
            if (tid < st) sh[tid] += sh[tid + st];
            __syncthreads();
        }
        s[zz] = sh[0];
        __syncthreads();
    }
    if (tid == 0){
        const int batch = *pbatch;
        float sc0 = s[0] / (float)Mrows + b2a[0];
        float sc1 = s[1] / (float)Mrows + b2b[0];
        float sc2 = s[2] / (float)batch + b2c[0];
        float sc3 = s[3] / (float)batch + b2d[0];
        float m = fmaxf(sc0, sc1);
        float e0 = expf(sc0 - m), e1 = expf(sc1 - m);
        g_w[0] = e0 / (e0 + e1); g_w[1] = e1 / (e0 + e1);
        m = fmaxf(sc2, sc3);
        e0 = expf(sc2 - m); e1 = expf(sc3 - m);
        g_w[2] = e0 / (e0 + e1); g_w[3] = e1 / (e0 + e1);
    }
}

// ============================ output assembly (mix rows only) ============================
__device__ __forceinline__ float4 ld4h(const __half* H, long u){
    const __half2* hp = (const __half2*)(H + u * 4);
    float2 a0 = __half22float2(hp[0]), a1 = __half22float2(hp[1]);
    return make_float4(a0.x, a0.y, a1.x, a1.y);
}

__global__ void k_output(const float4* __restrict__ S1T, const float4* __restrict__ S1S,
                         const float4* __restrict__ S2T, const float4* __restrict__ S2M,
                         const float4* __restrict__ S3T, const float4* __restrict__ S3M,
                         const int* __restrict__ pbatch,
                         float4* __restrict__ out, int NN)
{
    const int t = blockIdx.x * 256 + threadIdx.x;
    const int row = t >> 6;
    const int lane = t & 63;
    if (row >= NN) return;
    const int batch = *pbatch;
    const int j = g_inv[row];
    if (j < 0 && row >= batch) return;          // pure rows copied in k_gemm1
    const long o = (long)row * 64 + lane;
    const long sz = (long)NN * 64;

    if (j >= 0){
        const float w0 = g_w[0], w1 = g_w[1];
        long u = (long)j * 64 + lane;
        float4 a = ld4h(g_mH[0], u);
        float4 b = ld4h(g_mH[1], u);
        float4 m = make_float4(w0 * a.x + w1 * b.x, w0 * a.y + w1 * b.y,
                               w0 * a.z + w1 * b.z, w0 * a.w + w1 * b.w);
        out[0 * sz + o] = m; out[1 * sz + o] = m;
        out[2 * sz + o] = m; out[3 * sz + o] = m;
        out[4 * sz + o] = S3T[o]; out[5 * sz + o] = S3M[o];
    } else {
        const float w0 = g_w[2], w1 = g_w[3];
        float4 a = ld4h(g_rH[0], o);
        float4 b = ld4h(g_rH[1], o);
        float4 m = make_float4(w0 * a.x + w1 * b.x, w0 * a.y + w1 * b.y,
                               w0 * a.z + w1 * b.z, w0 * a.w + w1 * b.w);
        out[0 * sz + o] = S1T[o]; out[1 * sz + o] = S1S[o];
        out[2 * sz + o] = m; out[3 * sz + o] = m;
        out[4 * sz + o] = m; out[5 * sz + o] = m;
    }
}

// ============================ launch ============================
extern "C" void kernel_launch(void* const* d_in, const int* in_sizes, int n_in,
                              void* d_out, int out_size)
{
    const float* s1t  = (const float*)d_in[0];
    const float* s1s  = (const float*)d_in[1];
    const float* s2t  = (const float*)d_in[2];
    const float* s2me = (const float*)d_in[3];
    const float* s3t  = (const float*)d_in[4];
    const float* s3me = (const float*)d_in[5];
    const int*   mid    = (const int*)d_in[6];
    const int*   pbatch = (const int*)d_in[7];
    // d_in[8] = num (unused)
    const float* g1W = (const float*)d_in[9];
    const float* g1b = (const float*)d_in[10];
    const float* g2W = (const float*)d_in[11];
    const float* g2b = (const float*)d_in[12];
    const float* g3W = (const float*)d_in[13];
    const float* g3b = (const float*)d_in[14];
    const float* m1W1 = (const float*)d_in[15];
    const float* m1b1 = (const float*)d_in[16];
    const float* m1W2 = (const float*)d_in[17];
    const float* m1b2 = (const float*)d_in[18];
    const float* m2W1 = (const float*)d_in[19];
    const float* m2b1 = (const float*)d_in[20];
    const float* m2W2 = (const float*)d_in[21];
    const float* m2b2 = (const float*)d_in[22];
    const float* r1W1 = (const float*)d_in[23];
    const float* r1b1 = (const float*)d_in[24];
    const float* r1W2 = (const float*)d_in[25];
    const float* r1b2 = (const float*)d_in[26];
    const float* r2W1 = (const float*)d_in[27];
    const float* r2b1 = (const float*)d_in[28];
    const float* r2W2 = (const float*)d_in[29];
    const float* r2b2 = (const float*)d_in[30];

    const int NN = in_sizes[0] / HH;
    const int M  = in_sizes[6];
    const int ytiles = (NN + 127) / 128;
    const int cpyY = (NN + 511) / 512;   // copy rows per z-slice: cpyY*2 blocks * 64 rows

    cudaFuncSetAttribute(k_gemm1, cudaFuncAttributeMaxDynamicSharedMemorySize, G1_SMEM);

    k_wprep<<<dim3(8, 16, 8), dim3(32, 8)>>>(g1W, g2W, g3W,
                                             m1W1, m2W1, r1W1, r2W1, NN); // 1 (incl. inv init)
    k_inv_scat<<<(M + 255) / 256, 256>>>(mid, M);                        // 2

    k_gemm1<<<dim3(2, ytiles + cpyY, 4), 256, G1_SMEM>>>(
        s1t, s1s, s2t, s2me, s3t, s3me, mid, pbatch,
        g1b, g2b, g3b, M, ytiles, cpyY, (float4*)d_out, NN);             // 3
    k_gemm2<<<dim3(2, ytiles, 4), 256>>>(pbatch,
                         m1b1, m1W2, m2b1, m2W2,
                         r1b1, r1W2, r2b1, r2W2, M);                     // 4 <- profile target
    k_reduce<<<1, 256>>>(pbatch, M, ytiles * 2, m1b2, m2b2, r1b2, r2b2); // 5
    k_output<<<(NN * 64 + 255) / 256, 256>>>((const float4*)s1t, (const float4*)s1s,
                                             (const float4*)s2t, (const float4*)s2me,
                                             (const float4*)s3t, (const float4*)s3me,
                                             pbatch, (float4*)d_out, NN);    // 6
}

// round 16
// speedup vs baseline: 1.2960x; 1.2960x over previous
#include <cuda_runtime.h>
#include <cuda_fp16.h>
#include <math.h>
#include <stdint.h>

#define HH 256
#define PIT 80   // smem row pitch bytes: 5 x 16B -> conflict-free ldmatrix (5 coprime 8)

// ============================ helpers ============================
__device__ __forceinline__ uint32_t smem_u32(const void* p){
    uint32_t a;
    asm("{ .reg .u64 t; cvta.to.shared.u64 t, %1; cvt.u32.u64 %0, t; }" : "=r"(a) : "l"(p));
    return a;
}
__device__ __forceinline__ void ldsm4(uint32_t* d, uint32_t addr){
    asm volatile("ldmatrix.sync.aligned.m8n8.x4.shared.b16 {%0,%1,%2,%3}, [%4];"
        : "=r"(d[0]), "=r"(d[1]), "=r"(d[2]), "=r"(d[3]) : "r"(addr));
}
__device__ __forceinline__ void mma16816(float* c, const uint32_t* a, const uint32_t* b){
    asm volatile("mma.sync.aligned.m16n8k16.row.col.f32.f16.f16.f32 "
        "{%0,%1,%2,%3},{%4,%5,%6,%7},{%8,%9},{%0,%1,%2,%3};"
        : "+f"(c[0]), "+f"(c[1]), "+f"(c[2]), "+f"(c[3])
        : "r"(a[0]), "r"(a[1]), "r"(a[2]), "r"(a[3]), "r"(b[0]), "r"(b[1]));
}
__device__ __forceinline__ uint32_t pack_h2(float x0, float x1){
    __half2 h = __floats2half2_rn(x0, x1);
    uint32_t u; *(__half2*)&u = h; return u;
}
#define CPA16(d, s) asm volatile("cp.async.cg.shared.global [%0], [%1], 16;" :: "r"(d), "l"(s))
#define CP_COMMIT() asm volatile("cp.async.commit_group;" ::: "memory")
#define CP_WAIT0()  asm volatile("cp.async.wait_group 0;" ::: "memory")
#define CP_WAIT1()  asm volatile("cp.async.wait_group 1;" ::: "memory")

// ============================ device scratch ============================
__device__ __half g_WtH1[3][256 * 512];   // stage1 W^T fp16
__device__ __half g_WtH2[4][256 * 256];   // stage2 W1^T fp16
__device__ __half g_mH[2][16384 * HH];    // s1m, s2m (fp16)
__device__ __half g_rH[2][65536 * HH];    // s2r, s3r (fp16)
__device__ float g_part[4][2048];
__device__ float g_w[4];
__device__ int   g_inv[131072];

// ============================ tiny kernels ============================
__global__ void k_inv_init(int n){
    int i = blockIdx.x * 256 + threadIdx.x;
    if (i < n && i < 131072) g_inv[i] = -1;
}
__global__ void k_inv_scat(const int* __restrict__ mid, int m){
    int i = blockIdx.x * 256 + threadIdx.x;
    if (i < m) g_inv[mid[i]] = i;
}

// combined weight prep (fp16):
//   z in [0,3): stage-1 (K=512), z in [3,7): stage-2 (K=256, blockIdx.y<8)
__global__ void k_wprep(const float* __restrict__ g1W, const float* __restrict__ g2W,
                        const float* __restrict__ g3W,
                        const float* __restrict__ m1W1, const float* __restrict__ m2W1,
                        const float* __restrict__ r1W1, const float* __restrict__ r2W1){
    __shared__ float t[32][33];
    const int z = blockIdx.z;
    const bool st1 = (z < 3);
    if (!st1 && blockIdx.y >= 8) return;
    const float* W;
    switch (z){
        case 0: W = g1W; break;
        case 1: W = g2W; break;
        case 2: W = g3W; break;
        case 3: W = m1W1; break;
        case 4: W = m2W1; break;
        case 5: W = r1W1; break;
        default: W = r2W1; break;
    }
    const int K = st1 ? 512 : 256;
    __half* hi = st1 ? g_WtH1[z] : g_WtH2[z - 3];
    int n0 = blockIdx.x * 32, k0 = blockIdx.y * 32;
    int tx = threadIdx.x, ty = threadIdx.y;
#pragma unroll
    for (int i = 0; i < 4; i++){
        int r = ty + i * 8;
        t[r][tx] = W[(long)(k0 + r) * 256 + n0 + tx];
    }
    __syncthreads();
#pragma unroll
    for (int i = 0; i < 4; i++){
        int r = ty + i * 8;
        hi[(long)(n0 + r) * K + k0 + tx] = __float2half_rn(t[tx][r]);
    }
}

// ==== stage 1 GEMM + fused pure-row copy (R13 structure, batched ldcs/stcs) ====
// gemm: CTA tile 128x128, fp16 2-term, double-buffered, 2 CTA/SM
// blocks with blockIdx.y >= ytiles copy pure rows (inv<0 && row>=batch) of all 6 arrays
// dynamic smem: buf b at b*30720 { Ah@0, Al@10240, Bh@20480 }, bias @61440
#define G1_SMEM 62464
__global__ __launch_bounds__(256, 2)
void k_gemm1(const float* __restrict__ s1t, const float* __restrict__ s1s,
             const float* __restrict__ s2t, const float* __restrict__ s2me,
             const float* __restrict__ s3t, const float* __restrict__ s3me,
             const int* __restrict__ mid, const int* __restrict__ pbatch,
             const float* __restrict__ g1b, const float* __restrict__ g2b,
             const float* __restrict__ g3b, int Mrows,
             int ytiles, int cpyY, float4* __restrict__ out, int NN)
{
    extern __shared__ __align__(16) char smd[];
    const int z = blockIdx.z;
    const int batch = *pbatch;
    const int tid = threadIdx.x;

    // ---------------- fused copy path (loads batched, then stores) ----------------
    if ((int)blockIdx.y >= ytiles){
        const int cb = ((z * cpyY + ((int)blockIdx.y - ytiles)) * 2 + (int)blockIdx.x);
        const int row0c = cb * 64;
        const long sz = (long)NN * 64;
        const float4* S1T = (const float4*)s1t;
        const float4* S1S = (const float4*)s1s;
        const float4* S2T = (const float4*)s2t;
        const float4* S2M = (const float4*)s2me;
        const float4* S3T = (const float4*)s3t;
        const float4* S3M = (const float4*)s3me;
#pragma unroll 1
        for (int p = 0; p < 16; p++){
            int idx = p * 256 + tid;
            int r = row0c + (idx >> 6);
            int lane = idx & 63;
            if (r >= NN) break;
            if (g_inv[r] >= 0 || r < batch) continue;   // mix rows -> k_output
            long o = (long)r * 64 + lane;
            float4 v0 = __ldcs(S1T + o);
            float4 v1 = __ldcs(S1S + o);
            float4 v2 = __ldcs(S2T + o);
            float4 v3 = __ldcs(S2M + o);
            float4 v4 = __ldcs(S3T + o);
            float4 v5 = __ldcs(S3M + o);
            __stcs(out + 0 * sz + o, v0);
            __stcs(out + 1 * sz + o, v1);
            __stcs(out + 2 * sz + o, v2);
            __stcs(out + 3 * sz + o, v3);
            __stcs(out + 4 * sz + o, v4);
            __stcs(out + 5 * sz + o, v5);
        }
        return;
    }

    // ---------------- gemm path ----------------
    const int R = (z < 2) ? Mrows : batch;
    const int row0 = blockIdx.y * 128;
    if (row0 >= R) return;
    const int n0 = blockIdx.x * 128;

    const float *A0, *A1, *bias;
    const __half *WH;
    __half *OH;
    if (z == 0)      { A0 = s1t; A1 = s1s;  bias = g1b; WH = g_WtH1[0]; OH = g_mH[0]; }
    else if (z == 1) { A0 = s2t; A1 = s2me; bias = g2b; WH = g_WtH1[1]; OH = g_mH[1]; }
    else if (z == 2) { A0 = s2t; A1 = s2me; bias = g2b; WH = g_WtH1[1]; OH = g_rH[0]; }
    else             { A0 = s3t; A1 = s3me; bias = g3b; WH = g_WtH1[2]; OH = g_rH[1]; }

    float* biasS = (float*)(smd + 61440);
    const int lane = tid & 31, wid = tid >> 5;
    const int q = lane >> 3, lr = lane & 7, wm = wid & 3, wn = wid >> 2;
    biasS[tid] = bias[tid];

    const int arw = tid >> 1, ahalf = tid & 1;
    int gr = row0 + arw; if (gr >= R) gr = R - 1;
    const long arow = ((z < 2) ? (long)mid[gr] : (long)gr) * HH;

    const uint32_t sbase = smem_u32(smd);
    const int hrow = tid >> 1, half = tid & 1;
    const __half* pBH = WH + (long)(n0 + hrow) * 512 + half * 16;
    const uint32_t bdst0 = sbase + 20480u + (uint32_t)hrow * PIT + (uint32_t)half * 32;
    const uint32_t adst0 = sbase + (uint32_t)arw * PIT + (uint32_t)ahalf * 32;

    float acc[2][8][4];
#pragma unroll
    for (int i = 0; i < 2; i++)
#pragma unroll
        for (int j = 0; j < 8; j++)
#pragma unroll
            for (int k = 0; k < 4; k++) acc[i][j][k] = 0.f;

    float4 pa0, pa1, pa2, pa3;    // A staging: 16 fp32 for one 32-K chunk

#define LOADA(c) { \
    const float* src = (((c) < 8) ? A0 : A1) + arow + (((c) & 7) * 32 + ahalf * 16); \
    pa0 = ((const float4*)src)[0]; pa1 = ((const float4*)src)[1]; \
    pa2 = ((const float4*)src)[2]; pa3 = ((const float4*)src)[3]; }

#define STSA(b) { \
    float f[16]; \
    *(float4*)&f[0] = pa0; *(float4*)&f[4] = pa1; *(float4*)&f[8] = pa2; *(float4*)&f[12] = pa3; \
    uint32_t hb[8], lb[8]; \
    _Pragma("unroll") \
    for (int j = 0; j < 8; j++){ \
        float x0 = f[2*j], x1 = f[2*j+1]; \
        __half2 h2 = __floats2half2_rn(x0, x1); \
        hb[j] = *(uint32_t*)&h2; \
        lb[j] = pack_h2(x0 - __half2float(__low2half(h2)), \
                        x1 - __half2float(__high2half(h2))); \
    } \
    uint32_t off = (adst0 - sbase) + (uint32_t)(b) * 30720u; \
    *(uint4*)(smd + off)         = *(uint4*)&hb[0]; \
    *(uint4*)(smd + off + 16)    = *(uint4*)&hb[4]; \
    *(uint4*)(smd + off + 10240) = *(uint4*)&lb[0]; \
    *(uint4*)(smd + off + 10256) = *(uint4*)&lb[4]; }

#define ISSUEB(c, b) { \
    uint32_t d = bdst0 + (uint32_t)(b) * 30720u; \
    CPA16(d,      pBH + (c) * 32); CPA16(d + 16, pBH + (c) * 32 + 8); \
    CP_COMMIT(); }

    // prologue
    LOADA(0); STSA(0);
    ISSUEB(0, 0); ISSUEB(1, 1);
    LOADA(1);

    for (int c = 0; c < 16; c++){
        if (c >= 14) CP_WAIT0(); else CP_WAIT1();
        __syncthreads();                       // B(c) + A(c) visible; prior compute done
        const uint32_t bb = sbase + (uint32_t)(c & 1) * 30720u;
#pragma unroll
        for (int s = 0; s < 2; s++){
            uint32_t ah[2][4], al[2][4];
#pragma unroll
            for (int mt = 0; mt < 2; mt++){
                uint32_t ra = (uint32_t)(wm * 32 + mt * 16 + (q & 1) * 8 + lr) * PIT
                            + (uint32_t)(s * 2 + (q >> 1)) * 16;
                ldsm4(ah[mt], bb + ra);
                ldsm4(al[mt], bb + 10240 + ra);
            }
#pragma unroll
            for (int g = 0; g < 4; g++){
                uint32_t rb = (uint32_t)(wn * 64 + g * 16 + (q >> 1) * 8 + lr) * PIT
                            + (uint32_t)(s * 2 + (q & 1)) * 16;
                uint32_t bh[4];
                ldsm4(bh, bb + 20480 + rb);
                mma16816(acc[0][2*g],   ah[0], bh);
                mma16816(acc[1][2*g],   ah[1], bh);
                mma16816(acc[0][2*g+1], ah[0], bh + 2);
                mma16816(acc[1][2*g+1], ah[1], bh + 2);
                mma16816(acc[0][2*g],   al[0], bh);
                mma16816(acc[1][2*g],   al[1], bh);
                mma16816(acc[0][2*g+1], al[0], bh + 2);
                mma16816(acc[1][2*g+1], al[1], bh + 2);
            }
        }
        if (c + 1 < 16) STSA((c + 1) & 1);     // convert staged A(c+1) into other buffer
        if (c + 2 < 16) LOADA(c + 2);          // stage A(c+2)
        __syncthreads();                       // A(c+1) visible; buf c&1 free for B(c+2)
        if (c + 2 < 16) ISSUEB(c + 2, c & 1);
    }
#undef LOADA
#undef STSA
#undef ISSUEB

    // epilogue: tanh + bias, store fp16 (hi only)
#pragma unroll
    for (int mt = 0; mt < 2; mt++){
#pragma unroll
        for (int nt = 0; nt < 8; nt++){
            const int ccol = n0 + wn * 64 + nt * 8 + (lane & 3) * 2;
            const float b0 = biasS[ccol & 255], b1 = biasS[(ccol + 1) & 255];
#pragma unroll
            for (int hf = 0; hf < 2; hf++){
                int grow = row0 + wm * 32 + mt * 16 + (lane >> 2) + hf * 8;
                if (grow < R){
                    float x0 = tanhf(acc[mt][nt][hf * 2]     + b0);
                    float x1 = tanhf(acc[mt][nt][hf * 2 + 1] + b1);
                    *(uint32_t*)(OH + (long)grow * HH + ccol) = pack_h2(x0, x1);
                }
            }
        }
    }
}

// ============================ stage 2 GEMM (fp16 1-term, cp.async) ============
__global__ __launch_bounds__(256, 2)
void k_gemm2(const int* __restrict__ pbatch,
             const float* __restrict__ m1b1, const float* __restrict__ m1W2,
             const float* __restrict__ m2b1, const float* __restrict__ m2W2,
             const float* __restrict__ r1b1, const float* __restrict__ r1W2,
             const float* __restrict__ r2b1, const float* __restrict__ r2W2,
             int Mrows)
{
    const int z = blockIdx.z;
    const int batch = *pbatch;
    const int R = (z < 2) ? Mrows : batch;
    const int row0 = blockIdx.y * 128;
    const int tid = threadIdx.x;
    const int pidx = blockIdx.y * 2 + blockIdx.x;
    if (row0 >= R){ if (tid == 0) g_part[z][pidx] = 0.f; return; }
    const int n0 = blockIdx.x * 128;

    const __half *XH, *WH = g_WtH2[z];
    const float *b1, *W2;
    if (z == 0)      { XH = g_mH[0]; b1 = m1b1; W2 = m1W2; }
    else if (z == 1) { XH = g_mH[1]; b1 = m2b1; W2 = m2W2; }
    else if (z == 2) { XH = g_rH[0]; b1 = r1b1; W2 = r1W2; }
    else             { XH = g_rH[1]; b1 = r2b1; W2 = r2W2; }

    // buf b at b*20480 { Ah@0, Bh@10240 }; b1S@40960, w2S@41984, red@43008
    __shared__ __align__(16) char sm[44032];
    float* b1S = (float*)(sm + 40960);
    float* w2S = (float*)(sm + 41984);
    float* red = (float*)(sm + 43008);

    const int lane = tid & 31, wid = tid >> 5;
    const int q = lane >> 3, lr = lane & 7, wm = wid & 3, wn = wid >> 2;
    b1S[tid] = b1[tid];
    w2S[tid] = W2[tid];

    const uint32_t sbase = smem_u32(sm);
    const int hrow = tid >> 1, half = tid & 1;
    const __half* pA = XH + (long)(row0 + hrow) * 256 + half * 16;
    const __half* pB = WH + (long)(n0 + hrow) * 256 + half * 16;
    const uint32_t dst0 = sbase + (uint32_t)hrow * PIT + (uint32_t)half * 32;

#define ISSUE2(c, b) { \
    uint32_t d = dst0 + (uint32_t)(b) * 20480u; \
    CPA16(d,         pA + (c) * 32); CPA16(d + 16,    pA + (c) * 32 + 8); \
    CPA16(d + 10240, pB + (c) * 32); CPA16(d + 10256, pB + (c) * 32 + 8); \
    CP_COMMIT(); }

    float acc[2][8][4];
#pragma unroll
    for (int i = 0; i < 2; i++)
#pragma unroll
        for (int j = 0; j < 8; j++)
#pragma unroll
            for (int k = 0; k < 4; k++) acc[i][j][k] = 0.f;

    ISSUE2(0, 0); ISSUE2(1, 1);

    for (int c = 0; c < 8; c++){
        if (c >= 6) CP_WAIT0(); else CP_WAIT1();
        __syncthreads();
        const uint32_t bb = sbase + (uint32_t)(c & 1) * 20480u;
#pragma unroll
        for (int s = 0; s < 2; s++){
            uint32_t ah[2][4];
#pragma unroll
            for (int mt = 0; mt < 2; mt++){
                uint32_t ra = (uint32_t)(wm * 32 + mt * 16 + (q & 1) * 8 + lr) * PIT
                            + (uint32_t)(s * 2 + (q >> 1)) * 16;
                ldsm4(ah[mt], bb + ra);
            }
#pragma unroll
            for (int g = 0; g < 4; g++){
                uint32_t rb = (uint32_t)(wn * 64 + g * 16 + (q >> 1) * 8 + lr) * PIT
                            + (uint32_t)(s * 2 + (q & 1)) * 16;
                uint32_t bh[4];
                ldsm4(bh, bb + 10240 + rb);
                mma16816(acc[0][2*g],   ah[0], bh);
                mma16816(acc[1][2*g],   ah[1], bh);
                mma16816(acc[0][2*g+1], ah[0], bh + 2);
                mma16816(acc[1][2*g+1], ah[1], bh + 2);
            }
        }
        __syncthreads();
        if (c + 2 < 8) ISSUE2(c + 2, c & 1);
    }
#undef ISSUE2

    float local = 0.f;
#pragma unroll
    for (int mt = 0; mt < 2; mt++){
#pragma unroll
        for (int nt = 0; nt < 8; nt++){
            const int ccol = n0 + wn * 64 + nt * 8 + (lane & 3) * 2;
            const float b0 = b1S[ccol & 255], bb1 = b1S[(ccol + 1) & 255];
            const float w0 = w2S[ccol & 255], w1 = w2S[(ccol + 1) & 255];
#pragma unroll
            for (int hf = 0; hf < 2; hf++){
                int grow = row0 + wm * 32 + mt * 16 + (lane >> 2) + hf * 8;
                if (grow < R){
                    local += tanhf(acc[mt][nt][hf * 2]     + b0)  * w0;
                    local += tanhf(acc[mt][nt][hf * 2 + 1] + bb1) * w1;
                }
            }
        }
    }
    red[tid] = local;
    __syncthreads();
    for (int st = 128; st > 0; st >>= 1){        // fixed-order tree: deterministic
        if (tid < st) red[tid] += red[tid + st];
        __syncthreads();
    }
    if (tid == 0) g_part[z][pidx] = red[0];
}

// ============================ reduce + softmax ============================
__global__ void k_reduce(const int* __restrict__ pbatch, int Mrows, int ntiles,
                         const float* __restrict__ b2a, const float* __restrict__ b2b,
                         const float* __restrict__ b2c, const float* __restrict__ b2d)
{
    __shared__ float sh[256];
    const int tid = threadIdx.x;
    float s[4];
#pragma unroll
    for (int zz = 0; zz < 4; zz++){
        float loc = 0.f;
        for (int i = tid; i < ntiles; i += 256) loc += g_part[zz][i];
        sh[tid] = loc;
        __syncthreads();
        for (int st = 128; st > 0; st >>= 1){
            if (tid < st) sh[tid] += sh[tid + st];
            __syncthreads();
        }
        s[zz] = sh[0];
        __syncthreads();
    }
    if (tid == 0){
        const int batch = *pbatch;
        float sc0 = s[0] / (float)Mrows + b2a[0];
        float sc1 = s[1] / (float)Mrows + b2b[0];
        float sc2 = s[2] / (float)batch + b2c[0];
        float sc3 = s[3] / (float)batch + b2d[0];
        float m = fmaxf(sc0, sc1);
        float e0 = expf(sc0 - m), e1 = expf(sc1 - m);
        g_w[0] = e0 / (e0 + e1); g_w[1] = e1 / (e0 + e1);
        m = fmaxf(sc2, sc3);
        e0 = expf(sc2 - m); e1 = expf(sc3 - m);
        g_w[2] = e0 / (e0 + e1); g_w[3] = e1 / (e0 + e1);
    }
}

// ============================ output assembly (mix rows only) ============================
__device__ __forceinline__ float4 ld4h(const __half* H, long u){
    const __half2* hp = (const __half2*)(H + u * 4);
    float2 a0 = __half22float2(hp[0]), a1 = __half22float2(hp[1]);
    return make_float4(a0.x, a0.y, a1.x, a1.y);
}

__global__ void k_output(const float4* __restrict__ S1T, const float4* __restrict__ S1S,
                         const float4* __restrict__ S2T, const float4* __restrict__ S2M,
                         const float4* __restrict__ S3T, const float4* __restrict__ S3M,
                         const int* __restrict__ pbatch,
                         float4* __restrict__ out, int NN)
{
    const int t = blockIdx.x * 256 + threadIdx.x;
    const int row = t >> 6;
    const int lane = t & 63;
    if (row >= NN) return;
    const int batch = *pbatch;
    const int j = g_inv[row];
    if (j < 0 && row >= batch) return;          // pure rows copied in k_gemm1
    const long o = (long)row * 64 + lane;
    const long sz = (long)NN * 64;

    if (j >= 0){
        const float w0 = g_w[0], w1 = g_w[1];
        long u = (long)j * 64 + lane;
        float4 a = ld4h(g_mH[0], u);
        float4 b = ld4h(g_mH[1], u);
        float4 m = make_float4(w0 * a.x + w1 * b.x, w0 * a.y + w1 * b.y,
                               w0 * a.z + w1 * b.z, w0 * a.w + w1 * b.w);
        out[0 * sz + o] = m; out[1 * sz + o] = m;
        out[2 * sz + o] = m; out[3 * sz + o] = m;
        out[4 * sz + o] = S3T[o]; out[5 * sz + o] = S3M[o];
    } else {
        const float w0 = g_w[2], w1 = g_w[3];
        float4 a = ld4h(g_rH[0], o);
        float4 b = ld4h(g_rH[1], o);
        float4 m = make_float4(w0 * a.x + w1 * b.x, w0 * a.y + w1 * b.y,
                               w0 * a.z + w1 * b.z, w0 * a.w + w1 * b.w);
        out[0 * sz + o] = S1T[o]; out[1 * sz + o] = S1S[o];
        out[2 * sz + o] = m; out[3 * sz + o] = m;
        out[4 * sz + o] = m; out[5 * sz + o] = m;
    }
}

// ============================ launch ============================
extern "C" void kernel_launch(void* const* d_in, const int* in_sizes, int n_in,
                              void* d_out, int out_size)
{
    const float* s1t  = (const float*)d_in[0];
    const float* s1s  = (const float*)d_in[1];
    const float* s2t  = (const float*)d_in[2];
    const float* s2me = (const float*)d_in[3];
    const float* s3t  = (const float*)d_in[4];
    const float* s3me = (const float*)d_in[5];
    const int*   mid    = (const int*)d_in[6];
    const int*   pbatch = (const int*)d_in[7];
    // d_in[8] = num (unused)
    const float* g1W = (const float*)d_in[9];
    const float* g1b = (const float*)d_in[10];
    const float* g2W = (const float*)d_in[11];
    const float* g2b = (const float*)d_in[12];
    const float* g3W = (const float*)d_in[13];
    const float* g3b = (const float*)d_in[14];
    const float* m1W1 = (const float*)d_in[15];
    const float* m1b1 = (const float*)d_in[16];
    const float* m1W2 = (const float*)d_in[17];
    const float* m1b2 = (const float*)d_in[18];
    const float* m2W1 = (const float*)d_in[19];
    const float* m2b1 = (const float*)d_in[20];
    const float* m2W2 = (const float*)d_in[21];
    const float* m2b2 = (const float*)d_in[22];
    const float* r1W1 = (const float*)d_in[23];
    const float* r1b1 = (const float*)d_in[24];
    const float* r1W2 = (const float*)d_in[25];
    const float* r1b2 = (const float*)d_in[26];
    const float* r2W1 = (const float*)d_in[27];
    const float* r2b1 = (const float*)d_in[28];
    const float* r2W2 = (const float*)d_in[29];
    const float* r2b2 = (const float*)d_in[30];

    const int NN = in_sizes[0] / HH;
    const int M  = in_sizes[6];
    const int ytiles = (NN + 127) / 128;
    const int cpyY = (NN + 511) / 512;   // copy rows per z-slice: cpyY*2 blocks * 64 rows

    cudaFuncSetAttribute(k_gemm1, cudaFuncAttributeMaxDynamicSharedMemorySize, G1_SMEM);

    // launch order: gemm1 is my launch #4 (the ncu-captured position)
    k_inv_init<<<(NN + 255) / 256, 256>>>(NN);                           // 1
    k_inv_scat<<<(M + 255) / 256, 256>>>(mid, M);                        // 2
    k_wprep<<<dim3(8, 16, 7), dim3(32, 8)>>>(g1W, g2W, g3W,
                                             m1W1, m2W1, r1W1, r2W1);    // 3

    k_gemm1<<<dim3(2, ytiles + cpyY, 4), 256, G1_SMEM>>>(
        s1t, s1s, s2t, s2me, s3t, s3me, mid, pbatch,
        g1b, g2b, g3b, M, ytiles, cpyY, (float4*)d_out, NN);             // 4 <- profile target
    k_gemm2<<<dim3(2, ytiles, 4), 256>>>(pbatch,
                         m1b1, m1W2, m2b1, m2W2,
                         r1b1, r1W2, r2b1, r2W2, M);                     // 5
    k_reduce<<<1, 256>>>(pbatch, M, ytiles * 2, m1b2, m2b2, r1b2, r2b2); // 6
    k_output<<<(NN * 64 + 255) / 256, 256>>>((const float4*)s1t, (const float4*)s1s,
                                             (const float4*)s2t, (const float4*)s2me,
                                             (const float4*)s3t, (const float4*)s3me,
                                             pbatch, (float4*)d_out, NN);    // 7
}

// round 17
// speedup vs baseline: 1.3646x; 1.0529x over previous
#include <cuda_runtime.h>
#include <cuda_fp16.h>
#include <math.h>
#include <stdint.h>

#define HH 256
#define PIT 80   // smem row pitch bytes: 5 x 16B -> conflict-free ldmatrix (5 coprime 8)

// ============================ helpers ============================
__device__ __forceinline__ uint32_t smem_u32(const void* p){
    uint32_t a;
    asm("{ .reg .u64 t; cvta.to.shared.u64 t, %1; cvt.u32.u64 %0, t; }" : "=r"(a) : "l"(p));
    return a;
}
__device__ __forceinline__ void ldsm4(uint32_t* d, uint32_t addr){
    asm volatile("ldmatrix.sync.aligned.m8n8.x4.shared.b16 {%0,%1,%2,%3}, [%4];"
        : "=r"(d[0]), "=r"(d[1]), "=r"(d[2]), "=r"(d[3]) : "r"(addr));
}
__device__ __forceinline__ void mma16816(float* c, const uint32_t* a, const uint32_t* b){
    asm volatile("mma.sync.aligned.m16n8k16.row.col.f32.f16.f16.f32 "
        "{%0,%1,%2,%3},{%4,%5,%6,%7},{%8,%9},{%0,%1,%2,%3};"
        : "+f"(c[0]), "+f"(c[1]), "+f"(c[2]), "+f"(c[3])
        : "r"(a[0]), "r"(a[1]), "r"(a[2]), "r"(a[3]), "r"(b[0]), "r"(b[1]));
}
__device__ __forceinline__ uint32_t pack_h2(float x0, float x1){
    __half2 h = __floats2half2_rn(x0, x1);
    uint32_t u; *(__half2*)&u = h; return u;
}
#define CPA16(d, s) asm volatile("cp.async.cg.shared.global [%0], [%1], 16;" :: "r"(d), "l"(s))
#define CP_COMMIT() asm volatile("cp.async.commit_group;" ::: "memory")
#define CP_WAIT0()  asm volatile("cp.async.wait_group 0;" ::: "memory")
#define CP_WAIT1()  asm volatile("cp.async.wait_group 1;" ::: "memory")

// ============================ device scratch ============================
__device__ __half g_WtH1[3][256 * 512];   // stage1 W^T fp16
__device__ __half g_WtH2[4][256 * 256];   // stage2 W1^T fp16
__device__ __half g_mH[2][16384 * HH];    // s1m, s2m (fp16)
__device__ __half g_rH[2][65536 * HH];    // s2r, s3r (fp16)
__device__ float g_part[4][2048];
__device__ float g_w[4];
__device__ int   g_inv[131072];

// ============================ tiny kernels ============================
__global__ void k_inv_init(int n){
    int i = blockIdx.x * 256 + threadIdx.x;
    if (i < n && i < 131072) g_inv[i] = -1;
}
__global__ void k_inv_scat(const int* __restrict__ mid, int m){
    int i = blockIdx.x * 256 + threadIdx.x;
    if (i < m) g_inv[mid[i]] = i;
}

// combined weight prep (fp16):
//   z in [0,3): stage-1 (K=512), z in [3,7): stage-2 (K=256, blockIdx.y<8)
__global__ void k_wprep(const float* __restrict__ g1W, const float* __restrict__ g2W,
                        const float* __restrict__ g3W,
                        const float* __restrict__ m1W1, const float* __restrict__ m2W1,
                        const float* __restrict__ r1W1, const float* __restrict__ r2W1){
    __shared__ float t[32][33];
    const int z = blockIdx.z;
    const bool st1 = (z < 3);
    if (!st1 && blockIdx.y >= 8) return;
    const float* W;
    switch (z){
        case 0: W = g1W; break;
        case 1: W = g2W; break;
        case 2: W = g3W; break;
        case 3: W = m1W1; break;
        case 4: W = m2W1; break;
        case 5: W = r1W1; break;
        default: W = r2W1; break;
    }
    const int K = st1 ? 512 : 256;
    __half* hi = st1 ? g_WtH1[z] : g_WtH2[z - 3];
    int n0 = blockIdx.x * 32, k0 = blockIdx.y * 32;
    int tx = threadIdx.x, ty = threadIdx.y;
#pragma unroll
    for (int i = 0; i < 4; i++){
        int r = ty + i * 8;
        t[r][tx] = W[(long)(k0 + r) * 256 + n0 + tx];
    }
    __syncthreads();
#pragma unroll
    for (int i = 0; i < 4; i++){
        int r = ty + i * 8;
        hi[(long)(n0 + r) * K + k0 + tx] = __float2half_rn(t[tx][r]);
    }
}

// ==== stage 1 GEMM (fp16 1-term) + fused pure-row copy ====
// gemm: CTA tile 128x128, A and B both single fp16, double-buffered, 2 CTA/SM
// blocks with blockIdx.y >= ytiles copy pure rows (inv<0 && row>=batch) of all 6 arrays
// dynamic smem: buf b at b*20480 { Ah@0, Bh@10240 }, bias @40960
#define G1_SMEM 41984
__global__ __launch_bounds__(256, 2)
void k_gemm1(const float* __restrict__ s1t, const float* __restrict__ s1s,
             const float* __restrict__ s2t, const float* __restrict__ s2me,
             const float* __restrict__ s3t, const float* __restrict__ s3me,
             const int* __restrict__ mid, const int* __restrict__ pbatch,
             const float* __restrict__ g1b, const float* __restrict__ g2b,
             const float* __restrict__ g3b, int Mrows,
             int ytiles, int cpyY, float4* __restrict__ out, int NN)
{
    extern __shared__ __align__(16) char smd[];
    const int z = blockIdx.z;
    const int batch = *pbatch;
    const int tid = threadIdx.x;

    // ---------------- fused copy path (loads batched, then stores) ----------------
    if ((int)blockIdx.y >= ytiles){
        const int cb = ((z * cpyY + ((int)blockIdx.y - ytiles)) * 2 + (int)blockIdx.x);
        const int row0c = cb * 64;
        const long sz = (long)NN * 64;
        const float4* S1T = (const float4*)s1t;
        const float4* S1S = (const float4*)s1s;
        const float4* S2T = (const float4*)s2t;
        const float4* S2M = (const float4*)s2me;
        const float4* S3T = (const float4*)s3t;
        const float4* S3M = (const float4*)s3me;
#pragma unroll 1
        for (int p = 0; p < 16; p++){
            int idx = p * 256 + tid;
            int r = row0c + (idx >> 6);
            int lane = idx & 63;
            if (r >= NN) break;
            if (g_inv[r] >= 0 || r < batch) continue;   // mix rows -> k_output
            long o = (long)r * 64 + lane;
            float4 v0 = __ldcs(S1T + o);
            float4 v1 = __ldcs(S1S + o);
            float4 v2 = __ldcs(S2T + o);
            float4 v3 = __ldcs(S2M + o);
            float4 v4 = __ldcs(S3T + o);
            float4 v5 = __ldcs(S3M + o);
            __stcs(out + 0 * sz + o, v0);
            __stcs(out + 1 * sz + o, v1);
            __stcs(out + 2 * sz + o, v2);
            __stcs(out + 3 * sz + o, v3);
            __stcs(out + 4 * sz + o, v4);
            __stcs(out + 5 * sz + o, v5);
        }
        return;
    }

    // ---------------- gemm path ----------------
    const int R = (z < 2) ? Mrows : batch;
    const int row0 = blockIdx.y * 128;
    if (row0 >= R) return;
    const int n0 = blockIdx.x * 128;

    const float *A0, *A1, *bias;
    const __half *WH;
    __half *OH;
    if (z == 0)      { A0 = s1t; A1 = s1s;  bias = g1b; WH = g_WtH1[0]; OH = g_mH[0]; }
    else if (z == 1) { A0 = s2t; A1 = s2me; bias = g2b; WH = g_WtH1[1]; OH = g_mH[1]; }
    else if (z == 2) { A0 = s2t; A1 = s2me; bias = g2b; WH = g_WtH1[1]; OH = g_rH[0]; }
    else             { A0 = s3t; A1 = s3me; bias = g3b; WH = g_WtH1[2]; OH = g_rH[1]; }

    float* biasS = (float*)(smd + 40960);
    const int lane = tid & 31, wid = tid >> 5;
    const int q = lane >> 3, lr = lane & 7, wm = wid & 3, wn = wid >> 2;
    biasS[tid] = bias[tid];

    const int arw = tid >> 1, ahalf = tid & 1;
    int gr = row0 + arw; if (gr >= R) gr = R - 1;
    const long arow = ((z < 2) ? (long)mid[gr] : (long)gr) * HH;

    const uint32_t sbase = smem_u32(smd);
    const int hrow = tid >> 1, half = tid & 1;
    const __half* pBH = WH + (long)(n0 + hrow) * 512 + half * 16;
    const uint32_t bdst0 = sbase + 10240u + (uint32_t)hrow * PIT + (uint32_t)half * 32;
    const uint32_t adst0 = sbase + (uint32_t)arw * PIT + (uint32_t)ahalf * 32;

    float acc[2][8][4];
#pragma unroll
    for (int i = 0; i < 2; i++)
#pragma unroll
        for (int j = 0; j < 8; j++)
#pragma unroll
            for (int k = 0; k < 4; k++) acc[i][j][k] = 0.f;

    float4 pa0, pa1, pa2, pa3;    // A staging: 16 fp32 for one 32-K chunk

#define LOADA(c) { \
    const float* src = (((c) < 8) ? A0 : A1) + arow + (((c) & 7) * 32 + ahalf * 16); \
    pa0 = ((const float4*)src)[0]; pa1 = ((const float4*)src)[1]; \
    pa2 = ((const float4*)src)[2]; pa3 = ((const float4*)src)[3]; }

#define STSA(b) { \
    float f[16]; \
    *(float4*)&f[0] = pa0; *(float4*)&f[4] = pa1; *(float4*)&f[8] = pa2; *(float4*)&f[12] = pa3; \
    uint32_t hb[8]; \
    _Pragma("unroll") \
    for (int j = 0; j < 8; j++){ \
        __half2 h2 = __floats2half2_rn(f[2*j], f[2*j+1]); \
        hb[j] = *(uint32_t*)&h2; \
    } \
    uint32_t off = (adst0 - sbase) + (uint32_t)(b) * 20480u; \
    *(uint4*)(smd + off)      = *(uint4*)&hb[0]; \
    *(uint4*)(smd + off + 16) = *(uint4*)&hb[4]; }

#define ISSUEB(c, b) { \
    uint32_t d = bdst0 + (uint32_t)(b) * 20480u; \
    CPA16(d,      pBH + (c) * 32); CPA16(d + 16, pBH + (c) * 32 + 8); \
    CP_COMMIT(); }

    // prologue
    LOADA(0); STSA(0);
    ISSUEB(0, 0); ISSUEB(1, 1);
    LOADA(1);

    for (int c = 0; c < 16; c++){
        if (c >= 14) CP_WAIT0(); else CP_WAIT1();
        __syncthreads();                       // B(c) + A(c) visible; prior compute done
        const uint32_t bb = sbase + (uint32_t)(c & 1) * 20480u;
#pragma unroll
        for (int s = 0; s < 2; s++){
            uint32_t ah[2][4];
#pragma unroll
            for (int mt = 0; mt < 2; mt++){
                uint32_t ra = (uint32_t)(wm * 32 + mt * 16 + (q & 1) * 8 + lr) * PIT
                            + (uint32_t)(s * 2 + (q >> 1)) * 16;
                ldsm4(ah[mt], bb + ra);
            }
#pragma unroll
            for (int g = 0; g < 4; g++){
                uint32_t rb = (uint32_t)(wn * 64 + g * 16 + (q >> 1) * 8 + lr) * PIT
                            + (uint32_t)(s * 2 + (q & 1)) * 16;
                uint32_t bh[4];
                ldsm4(bh, bb + 10240 + rb);
                mma16816(acc[0][2*g],   ah[0], bh);
                mma16816(acc[1][2*g],   ah[1], bh);
                mma16816(acc[0][2*g+1], ah[0], bh + 2);
                mma16816(acc[1][2*g+1], ah[1], bh + 2);
            }
        }
        if (c + 1 < 16) STSA((c + 1) & 1);     // convert staged A(c+1) into other buffer
        if (c + 2 < 16) LOADA(c + 2);          // stage A(c+2)
        __syncthreads();                       // A(c+1) visible; buf c&1 free for B(c+2)
        if (c + 2 < 16) ISSUEB(c + 2, c & 1);
    }
#undef LOADA
#undef STSA
#undef ISSUEB

    // epilogue: tanh + bias, store fp16 (hi only)
#pragma unroll
    for (int mt = 0; mt < 2; mt++){
#pragma unroll
        for (int nt = 0; nt < 8; nt++){
            const int ccol = n0 + wn * 64 + nt * 8 + (lane & 3) * 2;
            const float b0 = biasS[ccol & 255], b1 = biasS[(ccol + 1) & 255];
#pragma unroll
            for (int hf = 0; hf < 2; hf++){
                int grow = row0 + wm * 32 + mt * 16 + (lane >> 2) + hf * 8;
                if (grow < R){
                    float x0 = tanhf(acc[mt][nt][hf * 2]     + b0);
                    float x1 = tanhf(acc[mt][nt][hf * 2 + 1] + b1);
                    *(uint32_t*)(OH + (long)grow * HH + ccol) = pack_h2(x0, x1);
                }
            }
        }
    }
}

// ============================ stage 2 GEMM (fp16 1-term, cp.async) ============
__global__ __launch_bounds__(256, 2)
void k_gemm2(const int* __restrict__ pbatch,
             const float* __restrict__ m1b1, const float* __restrict__ m1W2,
             const float* __restrict__ m2b1, const float* __restrict__ m2W2,
             const float* __restrict__ r1b1, const float* __restrict__ r1W2,
             const float* __restrict__ r2b1, const float* __restrict__ r2W2,
             int Mrows)
{
    const int z = blockIdx.z;
    const int batch = *pbatch;
    const int R = (z < 2) ? Mrows : batch;
    const int row0 = blockIdx.y * 128;
    const int tid = threadIdx.x;
    const int pidx = blockIdx.y * 2 + blockIdx.x;
    if (row0 >= R){ if (tid == 0) g_part[z][pidx] = 0.f; return; }
    const int n0 = blockIdx.x * 128;

    const __half *XH, *WH = g_WtH2[z];
    const float *b1, *W2;
    if (z == 0)      { XH = g_mH[0]; b1 = m1b1; W2 = m1W2; }
    else if (z == 1) { XH = g_mH[1]; b1 = m2b1; W2 = m2W2; }
    else if (z == 2) { XH = g_rH[0]; b1 = r1b1; W2 = r1W2; }
    else             { XH = g_rH[1]; b1 = r2b1; W2 = r2W2; }

    // buf b at b*20480 { Ah@0, Bh@10240 }; b1S@40960, w2S@41984, red@43008
    __shared__ __align__(16) char sm[44032];
    float* b1S = (float*)(sm + 40960);
    float* w2S = (float*)(sm + 41984);
    float* red = (float*)(sm + 43008);

    const int lane = tid & 31, wid = tid >> 5;
    const int q = lane >> 3, lr = lane & 7, wm = wid & 3, wn = wid >> 2;
    b1S[tid] = b1[tid];
    w2S[tid] = W2[tid];

    const uint32_t sbase = smem_u32(sm);
    const int hrow = tid >> 1, half = tid & 1;
    const __half* pA = XH + (long)(row0 + hrow) * 256 + half * 16;
    const __half* pB = WH + (long)(n0 + hrow) * 256 + half * 16;
    const uint32_t dst0 = sbase + (uint32_t)hrow * PIT + (uint32_t)half * 32;

#define ISSUE2(c, b) { \
    uint32_t d = dst0 + (uint32_t)(b) * 20480u; \
    CPA16(d,         pA + (c) * 32); CPA16(d + 16,    pA + (c) * 32 + 8); \
    CPA16(d + 10240, pB + (c) * 32); CPA16(d + 10256, pB + (c) * 32 + 8); \
    CP_COMMIT(); }

    float acc[2][8][4];
#pragma unroll
    for (int i = 0; i < 2; i++)
#pragma unroll
        for (int j = 0; j < 8; j++)
#pragma unroll
            for (int k = 0; k < 4; k++) acc[i][j][k] = 0.f;

    ISSUE2(0, 0); ISSUE2(1, 1);

    for (int c = 0; c < 8; c++){
        if (c >= 6) CP_WAIT0(); else CP_WAIT1();
        __syncthreads();
        const uint32_t bb = sbase + (uint32_t)(c & 1) * 20480u;
#pragma unroll
        for (int s = 0; s < 2; s++){
            uint32_t ah[2][4];
#pragma unroll
            for (int mt = 0; mt < 2; mt++){
                uint32_t ra = (uint32_t)(wm * 32 + mt * 16 + (q & 1) * 8 + lr) * PIT
                            + (uint32_t)(s * 2 + (q >> 1)) * 16;
                ldsm4(ah[mt], bb + ra);
            }
#pragma unroll
            for (int g = 0; g < 4; g++){
                uint32_t rb = (uint32_t)(wn * 64 + g * 16 + (q >> 1) * 8 + lr) * PIT
                            + (uint32_t)(s * 2 + (q & 1)) * 16;
                uint32_t bh[4];
                ldsm4(bh, bb + 10240 + rb);
                mma16816(acc[0][2*g],   ah[0], bh);
                mma16816(acc[1][2*g],   ah[1], bh);
                mma16816(acc[0][2*g+1], ah[0], bh + 2);
                mma16816(acc[1][2*g+1], ah[1], bh + 2);
            }
        }
        __syncthreads();
        if (c + 2 < 8) ISSUE2(c + 2, c & 1);
    }
#undef ISSUE2

    float local = 0.f;
#pragma unroll
    for (int mt = 0; mt < 2; mt++){
#pragma unroll
        for (int nt = 0; nt < 8; nt++){
            const int ccol = n0 + wn * 64 + nt * 8 + (lane & 3) * 2;
            const float b0 = b1S[ccol & 255], bb1 = b1S[(ccol + 1) & 255];
            const float w0 = w2S[ccol & 255], w1 = w2S[(ccol + 1) & 255];
#pragma unroll
            for (int hf = 0; hf < 2; hf++){
                int grow = row0 + wm * 32 + mt * 16 + (lane >> 2) + hf * 8;
                if (grow < R){
                    local += tanhf(acc[mt][nt][hf * 2]     + b0)  * w0;
                    local += tanhf(acc[mt][nt][hf * 2 + 1] + bb1) * w1;
                }
            }
        }
    }
    red[tid] = local;
    __syncthreads();
    for (int st = 128; st > 0; st >>= 1){        // fixed-order tree: deterministic
        if (tid < st) red[tid] += red[tid + st];
        __syncthreads();
    }
    if (tid == 0) g_part[z][pidx] = red[0];
}

// ============================ reduce + softmax ============================
__global__ void k_reduce(const int* __restrict__ pbatch, int Mrows, int ntiles,
                         const float* __restrict__ b2a, const float* __restrict__ b2b,
                         const float* __restrict__ b2c, const float* __restrict__ b2d)
{
    __shared__ float sh[256];
    const int tid = threadIdx.x;
    float s[4];
#pragma unroll
    for (int zz = 0; zz < 4; zz++){
        float loc = 0.f;
        for (int i = tid; i < ntiles; i += 256) loc += g_part[zz][i];
        sh[tid] = loc;
        __syncthreads();
        for (int st = 128; st > 0; st >>= 1){
            if (tid < st) sh[tid] += sh[tid + st];
            __syncthreads();
        }
        s[zz] = sh[0];
        __syncthreads();
    }
    if (tid == 0){
        const int batch = *pbatch;
        float sc0 = s[0] / (float)Mrows + b2a[0];
        float sc1 = s[1] / (float)Mrows + b2b[0];
        float sc2 = s[2] / (float)batch + b2c[0];
        float sc3 = s[3] / (float)batch + b2d[0];
        float m = fmaxf(sc0, sc1);
        float e0 = expf(sc0 - m), e1 = expf(sc1 - m);
        g_w[0] = e0 / (e0 + e1); g_w[1] = e1 / (e0 + e1);
        m = fmaxf(sc2, sc3);
        e0 = expf(sc2 - m); e1 = expf(sc3 - m);
        g_w[2] = e0 / (e0 + e1); g_w[3] = e1 / (e0 + e1);
    }
}

// ============================ output assembly (mix rows only) ============================
__device__ __forceinline__ float4 ld4h(const __half* H, long u){
    const __half2* hp = (const __half2*)(H + u * 4);
    float2 a0 = __half22float2(hp[0]), a1 = __half22float2(hp[1]);
    return make_float4(a0.x, a0.y, a1.x, a1.y);
}

__global__ void k_output(const float4* __restrict__ S1T, const float4* __restrict__ S1S,
                         const float4* __restrict__ S2T, const float4* __restrict__ S2M,
                         const float4* __restrict__ S3T, const float4* __restrict__ S3M,
                         const int* __restrict__ pbatch,
                         float4* __restrict__ out, int NN)
{
    const int t = blockIdx.x * 256 + threadIdx.x;
    const int row = t >> 6;
    const int lane = t & 63;
    if (row >= NN) return;
    const int batch = *pbatch;
    const int j = g_inv[row];
    if (j < 0 && row >= batch) return;          // pure rows copied in k_gemm1
    const long o = (long)row * 64 + lane;
    const long sz = (long)NN * 64;

    if (j >= 0){
        const float w0 = g_w[0], w1 = g_w[1];
        long u = (long)j * 64 + lane;
        float4 a = ld4h(g_mH[0], u);
        float4 b = ld4h(g_mH[1], u);
        float4 m = make_float4(w0 * a.x + w1 * b.x, w0 * a.y + w1 * b.y,
                               w0 * a.z + w1 * b.z, w0 * a.w + w1 * b.w);
        out[0 * sz + o] = m; out[1 * sz + o] = m;
        out[2 * sz + o] = m; out[3 * sz + o] = m;
        out[4 * sz + o] = S3T[o]; out[5 * sz + o] = S3M[o];
    } else {
        const float w0 = g_w[2], w1 = g_w[3];
        float4 a = ld4h(g_rH[0], o);
        float4 b = ld4h(g_rH[1], o);
        float4 m = make_float4(w0 * a.x + w1 * b.x, w0 * a.y + w1 * b.y,
                               w0 * a.z + w1 * b.z, w0 * a.w + w1 * b.w);
        out[0 * sz + o] = S1T[o]; out[1 * sz + o] = S1S[o];
        out[2 * sz + o] = m; out[3 * sz + o] = m;
        out[4 * sz + o] = m; out[5 * sz + o] = m;
    }
}

// ============================ launch ============================
extern "C" void kernel_launch(void* const* d_in, const int* in_sizes, int n_in,
                              void* d_out, int out_size)
{
    const float* s1t  = (const float*)d_in[0];
    const float* s1s  = (const float*)d_in[1];
    const float* s2t  = (const float*)d_in[2];
    const float* s2me = (const float*)d_in[3];
    const float* s3t  = (const float*)d_in[4];
    const float* s3me = (const float*)d_in[5];
    const int*   mid    = (const int*)d_in[6];
    const int*   pbatch = (const int*)d_in[7];
    // d_in[8] = num (unused)
    const float* g1W = (const float*)d_in[9];
    const float* g1b = (const float*)d_in[10];
    const float* g2W = (const float*)d_in[11];
    const float* g2b = (const float*)d_in[12];
    const float* g3W = (const float*)d_in[13];
    const float* g3b = (const float*)d_in[14];
    const float* m1W1 = (const float*)d_in[15];
    const float* m1b1 = (const float*)d_in[16];
    const float* m1W2 = (const float*)d_in[17];
    const float* m1b2 = (const float*)d_in[18];
    const float* m2W1 = (const float*)d_in[19];
    const float* m2b1 = (const float*)d_in[20];
    const float* m2W2 = (const float*)d_in[21];
    const float* m2b2 = (const float*)d_in[22];
    const float* r1W1 = (const float*)d_in[23];
    const float* r1b1 = (const float*)d_in[24];
    const float* r1W2 = (const float*)d_in[25];
    const float* r1b2 = (const float*)d_in[26];
    const float* r2W1 = (const float*)d_in[27];
    const float* r2b1 = (const float*)d_in[28];
    const float* r2W2 = (const float*)d_in[29];
    const float* r2b2 = (const float*)d_in[30];

    const int NN = in_sizes[0] / HH;
    const int M  = in_sizes[6];
    const int ytiles = (NN + 127) / 128;
    const int cpyY = (NN + 511) / 512;   // copy rows per z-slice: cpyY*2 blocks * 64 rows

    cudaFuncSetAttribute(k_gemm1, cudaFuncAttributeMaxDynamicSharedMemorySize, G1_SMEM);

    // launch order: gemm1 is my launch #4 (the ncu-captured position)
    k_inv_init<<<(NN + 255) / 256, 256>>>(NN);                           // 1
    k_inv_scat<<<(M + 255) / 256, 256>>>(mid, M);                        // 2
    k_wprep<<<dim3(8, 16, 7), dim3(32, 8)>>>(g1W, g2W, g3W,
                                             m1W1, m2W1, r1W1, r2W1);    // 3

    k_gemm1<<<dim3(2, ytiles + cpyY, 4), 256, G1_SMEM>>>(
        s1t, s1s, s2t, s2me, s3t, s3me, mid, pbatch,
        g1b, g2b, g3b, M, ytiles, cpyY, (float4*)d_out, NN);             // 4 <- profile target
    k_gemm2<<<dim3(2, ytiles, 4), 256>>>(pbatch,
                         m1b1, m1W2, m2b1, m2W2,
                         r1b1, r1W2, r2b1, r2W2, M);                     // 5
    k_reduce<<<1, 256>>>(pbatch, M, ytiles * 2, m1b2, m2b2, r1b2, r2b2); // 6
    k_output<<<(NN * 64 + 255) / 256, 256>>>((const float4*)s1t, (const float4*)s1s,
                                             (const float4*)s2t, (const float4*)s2me,
                                             (const float4*)s3t, (const float4*)s3me,
                                             pbatch, (float4*)d_out, NN);    // 7
}